// round 1
// baseline (speedup 1.0000x reference)
#include <cuda_runtime.h>
#include <cuda_bf16.h>
#include <math.h>

#define Bdim 2
#define Sdim 2048
#define Ddim 1024
#define Hdim 16
#define DHdim 64
#define NROWS (Bdim * Sdim)  // 4096

// Scratch (allocation-free contract: __device__ globals)
__device__ float g_q[NROWS * Ddim];
__device__ float g_k[NROWS * Ddim];
__device__ float g_v[NROWS * Ddim];
__device__ float g_ctx[NROWS * Ddim];
__device__ int   g_mask[NROWS];

// ---------------------------------------------------------------------------
// Mask dtype is ambiguous (jax bool -> int32 / uint8 / float32 on the wire).
// Detect from the first 4096 bytes (safe in every interpretation), expand to int.
// ---------------------------------------------------------------------------
__global__ void mask_expand_kernel(const void* __restrict__ mraw) {
    __shared__ int smode;
    if (threadIdx.x == 0) {
        const unsigned* w = (const unsigned*)mraw;
        int any_gt1 = 0, all_float = 1;
        for (int i = 0; i < 1024; ++i) {  // 4096 bytes, in-bounds for all dtypes
            unsigned v = w[i];
            if (v > 1u) any_gt1 = 1;
            if (v != 0u && v != 0x3F800000u) all_float = 0;
        }
        smode = any_gt1 ? (all_float ? 2 : 1) : 0;  // 0=int32, 1=byte, 2=float
    }
    __syncthreads();
    int mode = smode;
    for (int i = threadIdx.x; i < NROWS; i += blockDim.x) {
        int v;
        if (mode == 1)      v = ((const unsigned char*)mraw)[i] != 0;
        else if (mode == 2) v = ((const float*)mraw)[i] != 0.0f;
        else                v = ((const int*)mraw)[i] != 0;
        g_mask[i] = v;
    }
}

// ---------------------------------------------------------------------------
// Generic tiled SGEMM with bias: C[M,N] = A[M,K] @ W[K,N] + bias.
// BM=BN=64, BK=16, 256 threads, 4x4 register tile, float4 smem paths.
// M,N multiples of 64 and K multiple of 16 (true for all call sites).
// ---------------------------------------------------------------------------
#define BM 64
#define BN 64
#define BKs 16

__global__ __launch_bounds__(256)
void sgemm_bias_kernel(const float* __restrict__ A, const float* __restrict__ W,
                       const float* __restrict__ bias, float* __restrict__ C,
                       int M, int N, int K) {
    __shared__ float As[BKs][BM];
    __shared__ float Bs[BKs][BN];
    const int t  = threadIdx.x;
    const int tx = t & 15, ty = t >> 4;
    const int row0 = blockIdx.y * BM;
    const int col0 = blockIdx.x * BN;
    const int ar = t >> 2, ac4 = (t & 3) * 4;    // A-tile loader coords
    const int br = t >> 4, bc4 = (t & 15) * 4;   // W-tile loader coords
    float acc[4][4] = {};

    for (int kk = 0; kk < K; kk += BKs) {
        float4 av = *reinterpret_cast<const float4*>(&A[(size_t)(row0 + ar) * K + kk + ac4]);
        As[ac4 + 0][ar] = av.x; As[ac4 + 1][ar] = av.y;
        As[ac4 + 2][ar] = av.z; As[ac4 + 3][ar] = av.w;
        *reinterpret_cast<float4*>(&Bs[br][bc4]) =
            *reinterpret_cast<const float4*>(&W[(size_t)(kk + br) * N + col0 + bc4]);
        __syncthreads();
#pragma unroll
        for (int k = 0; k < BKs; ++k) {
            float4 a = *reinterpret_cast<const float4*>(&As[k][ty * 4]);
            float4 b = *reinterpret_cast<const float4*>(&Bs[k][tx * 4]);
            float ax[4] = {a.x, a.y, a.z, a.w};
            float bx[4] = {b.x, b.y, b.z, b.w};
#pragma unroll
            for (int i = 0; i < 4; ++i)
#pragma unroll
                for (int j = 0; j < 4; ++j) acc[i][j] += ax[i] * bx[j];
        }
        __syncthreads();
    }
#pragma unroll
    for (int i = 0; i < 4; ++i) {
        int r = row0 + ty * 4 + i;
#pragma unroll
        for (int j = 0; j < 4; ++j) {
            int c = col0 + tx * 4 + j;
            C[(size_t)r * N + c] = acc[i][j] + bias[c];
        }
    }
}

// ---------------------------------------------------------------------------
// scores[b,h,q,k] = (Qh @ Kh^T) / 8, masked on key axis; written raw into the
// attn region of d_out (softmax done in-place next).
// grid: (S/BN, S/BM, B*H)
// ---------------------------------------------------------------------------
__global__ __launch_bounds__(256)
void scores_kernel(float* __restrict__ attn) {
    const int bh = blockIdx.z;
    const int b  = bh / Hdim, h = bh % Hdim;
    const float* Q  = g_q + (size_t)b * Sdim * Ddim + h * DHdim;
    const float* Kp = g_k + (size_t)b * Sdim * Ddim + h * DHdim;
    float* Cr = attn + (size_t)bh * Sdim * Sdim;

    __shared__ float As[BKs][BM];
    __shared__ float Bs[BKs][BN];
    const int t  = threadIdx.x;
    const int tx = t & 15, ty = t >> 4;
    const int row0 = blockIdx.y * BM;
    const int col0 = blockIdx.x * BN;
    const int ar = t >> 2, ac4 = (t & 3) * 4;
    float acc[4][4] = {};

#pragma unroll
    for (int kk = 0; kk < DHdim; kk += BKs) {
        float4 av = *reinterpret_cast<const float4*>(&Q[(size_t)(row0 + ar) * Ddim + kk + ac4]);
        As[ac4 + 0][ar] = av.x; As[ac4 + 1][ar] = av.y;
        As[ac4 + 2][ar] = av.z; As[ac4 + 3][ar] = av.w;
        float4 bv = *reinterpret_cast<const float4*>(&Kp[(size_t)(col0 + ar) * Ddim + kk + ac4]);
        Bs[ac4 + 0][ar] = bv.x; Bs[ac4 + 1][ar] = bv.y;
        Bs[ac4 + 2][ar] = bv.z; Bs[ac4 + 3][ar] = bv.w;
        __syncthreads();
#pragma unroll
        for (int k = 0; k < BKs; ++k) {
            float4 a = *reinterpret_cast<const float4*>(&As[k][ty * 4]);
            float4 b2 = *reinterpret_cast<const float4*>(&Bs[k][tx * 4]);
            float ax[4] = {a.x, a.y, a.z, a.w};
            float bx[4] = {b2.x, b2.y, b2.z, b2.w};
#pragma unroll
            for (int i = 0; i < 4; ++i)
#pragma unroll
                for (int j = 0; j < 4; ++j) acc[i][j] += ax[i] * bx[j];
        }
        __syncthreads();
    }
#pragma unroll
    for (int i = 0; i < 4; ++i) {
        int r = row0 + ty * 4 + i;
#pragma unroll
        for (int j = 0; j < 4; ++j) {
            int c = col0 + tx * 4 + j;
            float s = acc[i][j] * 0.125f;
            if (!g_mask[b * Sdim + c]) s = -1e30f;
            Cr[(size_t)r * Sdim + c] = s;
        }
    }
}

// ---------------------------------------------------------------------------
// In-place row softmax over the last axis (2048). One block (256 thr) per row.
// ---------------------------------------------------------------------------
__global__ __launch_bounds__(256)
void softmax_kernel(float* __restrict__ attn) {
    const size_t row = blockIdx.x;
    float* p = attn + row * (size_t)Sdim;
    const int t = threadIdx.x;
    const int lane = t & 31, warp = t >> 5;
    __shared__ float red[8];

    float v[8];
    float4 v0 = *reinterpret_cast<const float4*>(&p[t * 8]);
    float4 v1 = *reinterpret_cast<const float4*>(&p[t * 8 + 4]);
    v[0] = v0.x; v[1] = v0.y; v[2] = v0.z; v[3] = v0.w;
    v[4] = v1.x; v[5] = v1.y; v[6] = v1.z; v[7] = v1.w;

    float m = v[0];
#pragma unroll
    for (int i = 1; i < 8; ++i) m = fmaxf(m, v[i]);
#pragma unroll
    for (int off = 16; off > 0; off >>= 1) m = fmaxf(m, __shfl_xor_sync(0xFFFFFFFFu, m, off));
    if (lane == 0) red[warp] = m;
    __syncthreads();
    m = red[0];
#pragma unroll
    for (int i = 1; i < 8; ++i) m = fmaxf(m, red[i]);
    __syncthreads();

    float s = 0.0f;
#pragma unroll
    for (int i = 0; i < 8; ++i) { v[i] = __expf(v[i] - m); s += v[i]; }
#pragma unroll
    for (int off = 16; off > 0; off >>= 1) s += __shfl_xor_sync(0xFFFFFFFFu, s, off);
    if (lane == 0) red[warp] = s;
    __syncthreads();
    s = red[0];
#pragma unroll
    for (int i = 1; i < 8; ++i) s += red[i];
    float inv = 1.0f / s;

    float4 o0 = make_float4(v[0] * inv, v[1] * inv, v[2] * inv, v[3] * inv);
    float4 o1 = make_float4(v[4] * inv, v[5] * inv, v[6] * inv, v[7] * inv);
    *reinterpret_cast<float4*>(&p[t * 8])     = o0;
    *reinterpret_cast<float4*>(&p[t * 8 + 4]) = o1;
}

// ---------------------------------------------------------------------------
// ctx[b,s,h*64+d] = sum_k attn[b,h,s,k] * V[b,k,h*64+d]
// grid: (1, S/BM, B*H). N-tile = 64 = DH exactly.
// ---------------------------------------------------------------------------
__global__ __launch_bounds__(256)
void ctx_kernel(const float* __restrict__ attn) {
    const int bh = blockIdx.z;
    const int b  = bh / Hdim, h = bh % Hdim;
    const float* A = attn + (size_t)bh * Sdim * Sdim;
    const float* V = g_v   + (size_t)b * Sdim * Ddim + h * DHdim;
    float* C       = g_ctx + (size_t)b * Sdim * Ddim + h * DHdim;

    __shared__ float As[BKs][BM];
    __shared__ float Bs[BKs][BN];
    const int t  = threadIdx.x;
    const int tx = t & 15, ty = t >> 4;
    const int row0 = blockIdx.y * BM;
    const int ar = t >> 2, ac4 = (t & 3) * 4;
    const int br = t >> 4, bc4 = (t & 15) * 4;
    float acc[4][4] = {};

    for (int kk = 0; kk < Sdim; kk += BKs) {
        float4 av = *reinterpret_cast<const float4*>(&A[(size_t)(row0 + ar) * Sdim + kk + ac4]);
        As[ac4 + 0][ar] = av.x; As[ac4 + 1][ar] = av.y;
        As[ac4 + 2][ar] = av.z; As[ac4 + 3][ar] = av.w;
        *reinterpret_cast<float4*>(&Bs[br][bc4]) =
            *reinterpret_cast<const float4*>(&V[(size_t)(kk + br) * Ddim + bc4]);
        __syncthreads();
#pragma unroll
        for (int k = 0; k < BKs; ++k) {
            float4 a = *reinterpret_cast<const float4*>(&As[k][ty * 4]);
            float4 b2 = *reinterpret_cast<const float4*>(&Bs[k][tx * 4]);
            float ax[4] = {a.x, a.y, a.z, a.w};
            float bx[4] = {b2.x, b2.y, b2.z, b2.w};
#pragma unroll
            for (int i = 0; i < 4; ++i)
#pragma unroll
                for (int j = 0; j < 4; ++j) acc[i][j] += ax[i] * bx[j];
        }
        __syncthreads();
    }
#pragma unroll
    for (int i = 0; i < 4; ++i) {
        int r = row0 + ty * 4 + i;
#pragma unroll
        for (int j = 0; j < 4; ++j) {
            C[(size_t)r * Ddim + tx * 4 + j] = acc[i][j];
        }
    }
}

// ---------------------------------------------------------------------------
extern "C" void kernel_launch(void* const* d_in, const int* in_sizes, int n_in,
                              void* d_out, int out_size) {
    const float* qs = (const float*)d_in[0];
    const float* ks = (const float*)d_in[1];
    const float* vs = (const float*)d_in[2];
    const void*  mk = d_in[3];
    const float* Wq = (const float*)d_in[4];
    const float* bq = (const float*)d_in[5];
    const float* Wk = (const float*)d_in[6];
    const float* bk = (const float*)d_in[7];
    const float* Wv = (const float*)d_in[8];
    const float* bv = (const float*)d_in[9];
    const float* Wo = (const float*)d_in[10];
    const float* bo = (const float*)d_in[11];

    float* out  = (float*)d_out;
    float* attn = out + (size_t)NROWS * Ddim;  // (out, attn) concatenated

    float *dq, *dk, *dv, *dctx;
    cudaGetSymbolAddress((void**)&dq,   g_q);
    cudaGetSymbolAddress((void**)&dk,   g_k);
    cudaGetSymbolAddress((void**)&dv,   g_v);
    cudaGetSymbolAddress((void**)&dctx, g_ctx);

    dim3 blk(256);
    mask_expand_kernel<<<1, 256>>>(mk);

    dim3 gproj(Ddim / BN, NROWS / BM);  // (16, 64)
    sgemm_bias_kernel<<<gproj, blk>>>(qs, Wq, bq, dq, NROWS, Ddim, Ddim);
    sgemm_bias_kernel<<<gproj, blk>>>(ks, Wk, bk, dk, NROWS, Ddim, Ddim);
    sgemm_bias_kernel<<<gproj, blk>>>(vs, Wv, bv, dv, NROWS, Ddim, Ddim);

    dim3 gsc(Sdim / BN, Sdim / BM, Bdim * Hdim);  // (32, 32, 32)
    scores_kernel<<<gsc, blk>>>(attn);

    softmax_kernel<<<Bdim * Hdim * Sdim, 256>>>(attn);  // 65536 rows

    dim3 gctx(1, Sdim / BM, Bdim * Hdim);  // (1, 32, 32)
    ctx_kernel<<<gctx, blk>>>(attn);

    sgemm_bias_kernel<<<gproj, blk>>>(dctx, Wo, bo, out, NROWS, Ddim, Ddim);
}

// round 2
// speedup vs baseline: 1.0013x; 1.0013x over previous
#include <cuda_runtime.h>
#include <cuda_bf16.h>
#include <math.h>

#define Bdim 2
#define Sdim 2048
#define Ddim 1024
#define Hdim 16
#define DHdim 64
#define NROWS (Bdim * Sdim)  // 4096

// Scratch (allocation-free contract: __device__ globals)
__device__ float g_q[NROWS * Ddim];
__device__ float g_k[NROWS * Ddim];
__device__ float g_v[NROWS * Ddim];
__device__ float g_ctx[NROWS * Ddim];
__device__ int   g_mask[NROWS];

// ---------------------------------------------------------------------------
// Mask dtype is ambiguous (jax bool -> int32 / uint8 / float32 on the wire).
// Detect from the first 4096 bytes (safe in every interpretation), expand to int.
// ---------------------------------------------------------------------------
__global__ void mask_expand_kernel(const void* __restrict__ mraw) {
    __shared__ int smode;
    if (threadIdx.x == 0) {
        const unsigned* w = (const unsigned*)mraw;
        int any_gt1 = 0, all_float = 1;
        for (int i = 0; i < 1024; ++i) {  // 4096 bytes, in-bounds for all dtypes
            unsigned v = w[i];
            if (v > 1u) any_gt1 = 1;
            if (v != 0u && v != 0x3F800000u) all_float = 0;
        }
        smode = any_gt1 ? (all_float ? 2 : 1) : 0;  // 0=int32, 1=byte, 2=float
    }
    __syncthreads();
    int mode = smode;
    for (int i = threadIdx.x; i < NROWS; i += blockDim.x) {
        int v;
        if (mode == 1)      v = ((const unsigned char*)mraw)[i] != 0;
        else if (mode == 2) v = ((const float*)mraw)[i] != 0.0f;
        else                v = ((const int*)mraw)[i] != 0;
        g_mask[i] = v;
    }
}

// ---------------------------------------------------------------------------
// Generic tiled SGEMM with bias: C[M,N] = A[M,K] @ W[K,N] + bias.
// BM=BN=64, BK=16, 256 threads, 4x4 register tile, float4 smem paths.
// M,N multiples of 64 and K multiple of 16 (true for all call sites).
// ---------------------------------------------------------------------------
#define BM 64
#define BN 64
#define BKs 16

__global__ __launch_bounds__(256)
void sgemm_bias_kernel(const float* __restrict__ A, const float* __restrict__ W,
                       const float* __restrict__ bias, float* __restrict__ C,
                       int M, int N, int K) {
    __shared__ float As[BKs][BM];
    __shared__ float Bs[BKs][BN];
    const int t  = threadIdx.x;
    const int tx = t & 15, ty = t >> 4;
    const int row0 = blockIdx.y * BM;
    const int col0 = blockIdx.x * BN;
    const int ar = t >> 2, ac4 = (t & 3) * 4;    // A-tile loader coords
    const int br = t >> 4, bc4 = (t & 15) * 4;   // W-tile loader coords
    float acc[4][4] = {};

    for (int kk = 0; kk < K; kk += BKs) {
        float4 av = *reinterpret_cast<const float4*>(&A[(size_t)(row0 + ar) * K + kk + ac4]);
        As[ac4 + 0][ar] = av.x; As[ac4 + 1][ar] = av.y;
        As[ac4 + 2][ar] = av.z; As[ac4 + 3][ar] = av.w;
        *reinterpret_cast<float4*>(&Bs[br][bc4]) =
            *reinterpret_cast<const float4*>(&W[(size_t)(kk + br) * N + col0 + bc4]);
        __syncthreads();
#pragma unroll
        for (int k = 0; k < BKs; ++k) {
            float4 a = *reinterpret_cast<const float4*>(&As[k][ty * 4]);
            float4 b = *reinterpret_cast<const float4*>(&Bs[k][tx * 4]);
            float ax[4] = {a.x, a.y, a.z, a.w};
            float bx[4] = {b.x, b.y, b.z, b.w};
#pragma unroll
            for (int i = 0; i < 4; ++i)
#pragma unroll
                for (int j = 0; j < 4; ++j) acc[i][j] += ax[i] * bx[j];
        }
        __syncthreads();
    }
#pragma unroll
    for (int i = 0; i < 4; ++i) {
        int r = row0 + ty * 4 + i;
#pragma unroll
        for (int j = 0; j < 4; ++j) {
            int c = col0 + tx * 4 + j;
            C[(size_t)r * N + c] = acc[i][j] + bias[c];
        }
    }
}

// ---------------------------------------------------------------------------
// scores[b,h,q,k] = (Qh @ Kh^T) / 8, masked on key axis; written raw into the
// attn region of d_out (softmax done in-place next).
// grid: (S/BN, S/BM, B*H)
// ---------------------------------------------------------------------------
__global__ __launch_bounds__(256)
void scores_kernel(float* __restrict__ attn) {
    const int bh = blockIdx.z;
    const int b  = bh / Hdim, h = bh % Hdim;
    const float* Q  = g_q + (size_t)b * Sdim * Ddim + h * DHdim;
    const float* Kp = g_k + (size_t)b * Sdim * Ddim + h * DHdim;
    float* Cr = attn + (size_t)bh * Sdim * Sdim;

    __shared__ float As[BKs][BM];
    __shared__ float Bs[BKs][BN];
    const int t  = threadIdx.x;
    const int tx = t & 15, ty = t >> 4;
    const int row0 = blockIdx.y * BM;
    const int col0 = blockIdx.x * BN;
    const int ar = t >> 2, ac4 = (t & 3) * 4;
    float acc[4][4] = {};

#pragma unroll
    for (int kk = 0; kk < DHdim; kk += BKs) {
        float4 av = *reinterpret_cast<const float4*>(&Q[(size_t)(row0 + ar) * Ddim + kk + ac4]);
        As[ac4 + 0][ar] = av.x; As[ac4 + 1][ar] = av.y;
        As[ac4 + 2][ar] = av.z; As[ac4 + 3][ar] = av.w;
        float4 bv = *reinterpret_cast<const float4*>(&Kp[(size_t)(col0 + ar) * Ddim + kk + ac4]);
        Bs[ac4 + 0][ar] = bv.x; Bs[ac4 + 1][ar] = bv.y;
        Bs[ac4 + 2][ar] = bv.z; Bs[ac4 + 3][ar] = bv.w;
        __syncthreads();
#pragma unroll
        for (int k = 0; k < BKs; ++k) {
            float4 a = *reinterpret_cast<const float4*>(&As[k][ty * 4]);
            float4 b2 = *reinterpret_cast<const float4*>(&Bs[k][tx * 4]);
            float ax[4] = {a.x, a.y, a.z, a.w};
            float bx[4] = {b2.x, b2.y, b2.z, b2.w};
#pragma unroll
            for (int i = 0; i < 4; ++i)
#pragma unroll
                for (int j = 0; j < 4; ++j) acc[i][j] += ax[i] * bx[j];
        }
        __syncthreads();
    }
#pragma unroll
    for (int i = 0; i < 4; ++i) {
        int r = row0 + ty * 4 + i;
#pragma unroll
        for (int j = 0; j < 4; ++j) {
            int c = col0 + tx * 4 + j;
            float s = acc[i][j] * 0.125f;
            if (!g_mask[b * Sdim + c]) s = -1e30f;
            Cr[(size_t)r * Sdim + c] = s;
        }
    }
}

// ---------------------------------------------------------------------------
// In-place row softmax over the last axis (2048). One block (256 thr) per row.
// ---------------------------------------------------------------------------
__global__ __launch_bounds__(256)
void softmax_kernel(float* __restrict__ attn) {
    const size_t row = blockIdx.x;
    float* p = attn + row * (size_t)Sdim;
    const int t = threadIdx.x;
    const int lane = t & 31, warp = t >> 5;
    __shared__ float red[8];

    float v[8];
    float4 v0 = *reinterpret_cast<const float4*>(&p[t * 8]);
    float4 v1 = *reinterpret_cast<const float4*>(&p[t * 8 + 4]);
    v[0] = v0.x; v[1] = v0.y; v[2] = v0.z; v[3] = v0.w;
    v[4] = v1.x; v[5] = v1.y; v[6] = v1.z; v[7] = v1.w;

    float m = v[0];
#pragma unroll
    for (int i = 1; i < 8; ++i) m = fmaxf(m, v[i]);
#pragma unroll
    for (int off = 16; off > 0; off >>= 1) m = fmaxf(m, __shfl_xor_sync(0xFFFFFFFFu, m, off));
    if (lane == 0) red[warp] = m;
    __syncthreads();
    m = red[0];
#pragma unroll
    for (int i = 1; i < 8; ++i) m = fmaxf(m, red[i]);
    __syncthreads();

    float s = 0.0f;
#pragma unroll
    for (int i = 0; i < 8; ++i) { v[i] = __expf(v[i] - m); s += v[i]; }
#pragma unroll
    for (int off = 16; off > 0; off >>= 1) s += __shfl_xor_sync(0xFFFFFFFFu, s, off);
    if (lane == 0) red[warp] = s;
    __syncthreads();
    s = red[0];
#pragma unroll
    for (int i = 1; i < 8; ++i) s += red[i];
    float inv = 1.0f / s;

    float4 o0 = make_float4(v[0] * inv, v[1] * inv, v[2] * inv, v[3] * inv);
    float4 o1 = make_float4(v[4] * inv, v[5] * inv, v[6] * inv, v[7] * inv);
    *reinterpret_cast<float4*>(&p[t * 8])     = o0;
    *reinterpret_cast<float4*>(&p[t * 8 + 4]) = o1;
}

// ---------------------------------------------------------------------------
// ctx[b,s,h*64+d] = sum_k attn[b,h,s,k] * V[b,k,h*64+d]
// grid: (1, S/BM, B*H). N-tile = 64 = DH exactly.
// ---------------------------------------------------------------------------
__global__ __launch_bounds__(256)
void ctx_kernel(const float* __restrict__ attn) {
    const int bh = blockIdx.z;
    const int b  = bh / Hdim, h = bh % Hdim;
    const float* A = attn + (size_t)bh * Sdim * Sdim;
    const float* V = g_v   + (size_t)b * Sdim * Ddim + h * DHdim;
    float* C       = g_ctx + (size_t)b * Sdim * Ddim + h * DHdim;

    __shared__ float As[BKs][BM];
    __shared__ float Bs[BKs][BN];
    const int t  = threadIdx.x;
    const int tx = t & 15, ty = t >> 4;
    const int row0 = blockIdx.y * BM;
    const int ar = t >> 2, ac4 = (t & 3) * 4;
    const int br = t >> 4, bc4 = (t & 15) * 4;
    float acc[4][4] = {};

    for (int kk = 0; kk < Sdim; kk += BKs) {
        float4 av = *reinterpret_cast<const float4*>(&A[(size_t)(row0 + ar) * Sdim + kk + ac4]);
        As[ac4 + 0][ar] = av.x; As[ac4 + 1][ar] = av.y;
        As[ac4 + 2][ar] = av.z; As[ac4 + 3][ar] = av.w;
        *reinterpret_cast<float4*>(&Bs[br][bc4]) =
            *reinterpret_cast<const float4*>(&V[(size_t)(kk + br) * Ddim + bc4]);
        __syncthreads();
#pragma unroll
        for (int k = 0; k < BKs; ++k) {
            float4 a = *reinterpret_cast<const float4*>(&As[k][ty * 4]);
            float4 b2 = *reinterpret_cast<const float4*>(&Bs[k][tx * 4]);
            float ax[4] = {a.x, a.y, a.z, a.w};
            float bx[4] = {b2.x, b2.y, b2.z, b2.w};
#pragma unroll
            for (int i = 0; i < 4; ++i)
#pragma unroll
                for (int j = 0; j < 4; ++j) acc[i][j] += ax[i] * bx[j];
        }
        __syncthreads();
    }
#pragma unroll
    for (int i = 0; i < 4; ++i) {
        int r = row0 + ty * 4 + i;
#pragma unroll
        for (int j = 0; j < 4; ++j) {
            C[(size_t)r * Ddim + tx * 4 + j] = acc[i][j];
        }
    }
}

// ---------------------------------------------------------------------------
extern "C" void kernel_launch(void* const* d_in, const int* in_sizes, int n_in,
                              void* d_out, int out_size) {
    const float* qs = (const float*)d_in[0];
    const float* ks = (const float*)d_in[1];
    const float* vs = (const float*)d_in[2];
    const void*  mk = d_in[3];
    const float* Wq = (const float*)d_in[4];
    const float* bq = (const float*)d_in[5];
    const float* Wk = (const float*)d_in[6];
    const float* bk = (const float*)d_in[7];
    const float* Wv = (const float*)d_in[8];
    const float* bv = (const float*)d_in[9];
    const float* Wo = (const float*)d_in[10];
    const float* bo = (const float*)d_in[11];

    float* out  = (float*)d_out;
    float* attn = out + (size_t)NROWS * Ddim;  // (out, attn) concatenated

    float *dq, *dk, *dv, *dctx;
    cudaGetSymbolAddress((void**)&dq,   g_q);
    cudaGetSymbolAddress((void**)&dk,   g_k);
    cudaGetSymbolAddress((void**)&dv,   g_v);
    cudaGetSymbolAddress((void**)&dctx, g_ctx);

    dim3 blk(256);
    mask_expand_kernel<<<1, 256>>>(mk);

    dim3 gproj(Ddim / BN, NROWS / BM);  // (16, 64)
    sgemm_bias_kernel<<<gproj, blk>>>(qs, Wq, bq, dq, NROWS, Ddim, Ddim);
    sgemm_bias_kernel<<<gproj, blk>>>(ks, Wk, bk, dk, NROWS, Ddim, Ddim);
    sgemm_bias_kernel<<<gproj, blk>>>(vs, Wv, bv, dv, NROWS, Ddim, Ddim);

    dim3 gsc(Sdim / BN, Sdim / BM, Bdim * Hdim);  // (32, 32, 32)
    scores_kernel<<<gsc, blk>>>(attn);

    softmax_kernel<<<Bdim * Hdim * Sdim, 256>>>(attn);  // 65536 rows

    dim3 gctx(1, Sdim / BM, Bdim * Hdim);  // (1, 32, 32)
    ctx_kernel<<<gctx, blk>>>(attn);

    sgemm_bias_kernel<<<gproj, blk>>>(dctx, Wo, bo, out, NROWS, Ddim, Ddim);
}